// round 13
// baseline (speedup 1.0000x reference)
#include <cuda_runtime.h>
#include <cuda_bf16.h>
#include <cstdint>

#define NF       32
#define NPOLY    6545
#define BATCH    8192
#define MTILE    64
#define NTILES   (BATCH / MTILE)   // 128
#define NRUNS    561
#define NCHUNKP  465               // real chunks (7428 used slots, padded runs)
#define NCHUNKF  466               // +1 ghost chunk (defaults) for branch-free prefetch
#define KPADX    (NCHUNKF * 16)    // 7456 logical slots incl. ghost
#define NSPLIT   6
#define THREADS  128

__device__ int                g_slot2p[KPADX];               // logical slot -> monomial p (-1 = pad)
__device__ unsigned long long g_sched[NCHUNKF * 4];          // [chunk][q]: f|g<<8|m0<<16|m1<<24|m2<<32|m3<<40
__device__ unsigned long long g_wfrag[NCHUNKF * 2 * 32 * 4]; // [chunk][plane][lane][nt] -> {reg0,reg1}
__device__ float              g_part[NSPLIT][BATCH * NF];    // K-split partials
__device__ int                g_cnt[NTILES];                 // per-tile arrival counters

// ---------------------------------------------------------------------------
// One thread per run (runs have constant h = x_f * x_g):
//   run 0: level<=1, (f,g)=(32,32), L=33, m-list = {32, 0..31}, p = 0..32
//   runs 1..32: level2, f=0..31, g=32, L=f+1, m=0..f, p = 33 + T2(f) + m
//   runs 33..560: level3, (f,g) lex, L=g+1, m=0..g, p = 561 + T3(f) + T2(g) + m
// Runs padded to multiples of 4; a group of 4 logical slots = one (chunk,q)
// sched word; physical k-slot = 2q + (e&1) + 8*(e>>1) for group element e.
// Thread 0 also writes tail/ghost defaults; threads <NTILES zero counters.
// ---------------------------------------------------------------------------
__global__ void build_sched_kernel() {
    int r = blockIdx.x * blockDim.x + threadIdx.x;
    if (r >= NRUNS) return;

    if (r < NTILES) g_cnt[r] = 0;
    if (r == 0) {
        for (int w = 1857; w < NCHUNKF * 4; ++w) g_sched[w] = 0x0000202020202020ull;
        for (int s = 7428; s < KPADX; ++s) g_slot2p[s] = -1;
    }

    int f, g, L, base_p, off;
    if (r == 0) {
        f = 32; g = 32; L = 33; base_p = 0; off = 0;
    } else if (r <= 32) {
        int ff = r - 1;
        f = ff; g = 32; L = ff + 1;
        base_p = 33 + ff * (ff + 1) / 2;
        off = 36;
        for (int t = 0; t < ff; ++t) off += ((t + 4) / 4) * 4;   // ceil((t+1)/4)*4
    } else {
        int rr = r - 33;                       // = f(f+1)/2 + g
        int ff = (int)((sqrtf(8.0f * (float)rr + 1.0f) - 1.0f) * 0.5f);
        if (ff < 0) ff = 0; if (ff > 31) ff = 31;
        while (ff < 31 && (ff + 1) * (ff + 2) / 2 <= rr) ff++;
        while (ff > 0 && ff * (ff + 1) / 2 > rr) ff--;
        int gg = rr - ff * (ff + 1) / 2;
        f = ff; g = gg; L = gg + 1;
        base_p = 561 + ff * (ff + 1) * (ff + 2) / 6 + gg * (gg + 1) / 2;
        off = 612;                             // 36 + 576 (levels <=2 padded)
        for (int t = 0; t < ff; ++t)
            for (int u = 0; u <= t; ++u) off += ((u + 4) / 4) * 4;
        for (int u = 0; u < gg; ++u) off += ((u + 4) / 4) * 4;
    }

    int P = ((L + 3) / 4) * 4;
    for (int i0 = 0; i0 < P; i0 += 4) {
        unsigned long long sc = (unsigned long long)f | ((unsigned long long)g << 8);
#pragma unroll
        for (int e = 0; e < 4; ++e) {
            int i = i0 + e;
            int m, p;
            if (r == 0) {
                if (i == 0)      { m = 32;    p = 0; }
                else if (i < L)  { m = i - 1; p = i; }
                else             { m = 32;    p = -1; }
            } else {
                if (i < L)       { m = i;     p = base_p + i; }
                else             { m = 32;    p = -1; }
            }
            sc |= (unsigned long long)m << (16 + 8 * e);
            g_slot2p[off + i] = p;
        }
        int s = off + i0;
        g_sched[(s >> 4) * 4 + ((s >> 2) & 3)] = sc;
    }
}

// W fragments for mma.m16n8k16.row.col B (col-major KxN), hi/lo bf16 planes.
// Lane-major layout: [chunk][plane][lane][nt] so the 4 n-tiles of one lane
// are 32 contiguous bytes -> 2x LDG.128 per plane in the consumer.
// Physical k-slot (2q + j + 8*half) <- logical slot c*16 + q*4 + j + 2*half.
__global__ void build_wfrag_kernel(const float* __restrict__ W) {
    int e = blockIdx.x * blockDim.x + threadIdx.x;
    if (e >= NCHUNKF * 2 * 32 * 4) return;
    int nt   = e & 3;
    int lane = (e >> 2) & 31;
    int pl   = (e >> 7) & 1;
    int c    = e >> 8;
    int q    = lane & 3;
    int n    = nt * 8 + (lane >> 2);

    unsigned long long out = 0;
#pragma unroll
    for (int half = 0; half < 2; ++half) {
        uint32_t reg = 0;
#pragma unroll
        for (int j = 0; j < 2; ++j) {
            int s = c * 16 + q * 4 + j + 2 * half;
            int p = g_slot2p[s];
            float w = (p >= 0) ? W[p * NF + n] : 0.0f;
            __nv_bfloat16 h = __float2bfloat16(w);
            __nv_bfloat16 val = (pl == 0) ? h : __float2bfloat16(w - __bfloat162float(h));
            reg |= (uint32_t)__bfloat16_as_ushort(val) << (16 * j);
        }
        out |= (unsigned long long)reg << (32 * half);
    }
    g_wfrag[e] = out;
}

// ---------------------------------------------------------------------------
__device__ __forceinline__ void mma16816(float* d, const uint32_t* a,
                                         uint32_t b0, uint32_t b1) {
    asm("mma.sync.aligned.m16n8k16.row.col.f32.bf16.bf16.f32 "
        "{%0,%1,%2,%3}, {%4,%5,%6,%7}, {%8,%9}, {%0,%1,%2,%3};"
        : "+f"(d[0]), "+f"(d[1]), "+f"(d[2]), "+f"(d[3])
        : "r"(a[0]), "r"(a[1]), "r"(a[2]), "r"(a[3]), "r"(b0), "r"(b1));
}

__device__ __forceinline__ uint32_t packbf2(float lo, float hi) {
    __nv_bfloat162 t = __floats2bfloat162_rn(lo, hi);   // .x = lo half
    return *(uint32_t*)&t;
}

// ---------------------------------------------------------------------------
// Main fused kernel: CTA = 64-row M-tile x one K-sixth. 4 warps, each a
// 16-row stripe x full N=32. Per chunk per thread: shared h = x_f*x_g ->
// 12 LDS + 10 FMUL. Last CTA per tile performs the cross-split reduction.
// ---------------------------------------------------------------------------
__global__ __launch_bounds__(THREADS, 6)
void taylor_mma_kernel(const float* __restrict__ x, float* __restrict__ out) {
    __shared__ float xt[33][65];   // row stride 65: bank = feat + row (mod 32)
    __shared__ int amLast;

    const int tid   = threadIdx.x;
    const int lane  = tid & 31;
    const int warp  = tid >> 5;          // 0..3
    const int gid   = lane >> 2;         // 0..7
    const int q     = lane & 3;          // 0..3
    const int tile  = blockIdx.x / NSPLIT;
    const int split = blockIdx.x % NSPLIT;
    const int row0  = tile * MTILE;
    const int r0    = warp * 16 + gid;
    const int r1    = r0 + 8;

    for (int e = tid; e < MTILE * NF; e += THREADS) {
        int rr = e >> 5, ii = e & 31;
        xt[ii][rr] = x[(row0 + rr) * NF + ii];
    }
    if (tid < MTILE) xt[32][tid] = 1.0f;
    __syncthreads();

    float acc[4][4];
#pragma unroll
    for (int nt = 0; nt < 4; ++nt)
#pragma unroll
        for (int j = 0; j < 4; ++j) acc[nt][j] = 0.0f;

    // 465 = 6*77 + 3 -> splits 0..2 take 78 chunks, 3..5 take 77
    const int cbase = 77 * split + (split < 3 ? split : 3);
    const int nch   = 77 + (split < 3 ? 1 : 0);
    const float* xr0 = &xt[0][r0];
    const float* xr1 = &xt[0][r1];

    // ---- prologue: load chunk cbase ----
    unsigned long long sc_cur = g_sched[cbase * 4 + q];
    ulonglong2 Bh01, Bh23, Bl01, Bl23;
    {
        const ulonglong2* wh = (const ulonglong2*)(g_wfrag + (((size_t)cbase * 2 + 0) * 32 + lane) * 4);
        const ulonglong2* wl = (const ulonglong2*)(g_wfrag + (((size_t)cbase * 2 + 1) * 32 + lane) * 4);
        Bh01 = wh[0]; Bh23 = wh[1];
        Bl01 = wl[0]; Bl23 = wl[1];
    }

#pragma unroll 2
    for (int i = 0; i < nch; ++i) {
        // ---- prefetch chunk i+1 (ghost chunk makes this always valid) ----
        const int cn = cbase + i + 1;
        const unsigned long long sc_nxt = g_sched[cn * 4 + q];
        const ulonglong2* whn = (const ulonglong2*)(g_wfrag + (((size_t)cn * 2 + 0) * 32 + lane) * 4);
        const ulonglong2* wln = (const ulonglong2*)(g_wfrag + (((size_t)cn * 2 + 1) * 32 + lane) * 4);
        const ulonglong2 nBh01 = whn[0], nBh23 = whn[1];
        const ulonglong2 nBl01 = wln[0], nBl23 = wln[1];

        // ---- evaluate: one shared h per row, 4 m-multiplies per row ----
        const int f  = (int)(sc_cur & 255);
        const int g  = (int)((sc_cur >> 8) & 255);
        const int m0 = (int)((sc_cur >> 16) & 255);
        const int m1 = (int)((sc_cur >> 24) & 255);
        const int m2 = (int)((sc_cur >> 32) & 255);
        const int m3 = (int)((sc_cur >> 40) & 255);
        const float h0 = xr0[f * 65] * xr0[g * 65];
        const float h1 = xr1[f * 65] * xr1[g * 65];
        float v0[4], v1[4];
        v0[0] = h0 * xr0[m0 * 65];  v1[0] = h1 * xr1[m0 * 65];
        v0[1] = h0 * xr0[m1 * 65];  v1[1] = h1 * xr1[m1 * 65];
        v0[2] = h0 * xr0[m2 * 65];  v1[2] = h1 * xr1[m2 * 65];
        v0[3] = h0 * xr0[m3 * 65];  v1[3] = h1 * xr1[m3 * 65];

        // ---- A fragments: hi plane + residual lo plane ----
        uint32_t Ah[4], Al[4];
        Ah[0] = packbf2(v0[0], v0[1]);
        Ah[1] = packbf2(v1[0], v1[1]);
        Ah[2] = packbf2(v0[2], v0[3]);
        Ah[3] = packbf2(v1[2], v1[3]);
#pragma unroll
        for (int hh = 0; hh < 2; ++hh) {
            {
                uint32_t u = Ah[hh * 2];
                float f0 = __uint_as_float(u << 16);
                float f1 = __uint_as_float(u & 0xffff0000u);
                Al[hh * 2] = packbf2(v0[hh * 2] - f0, v0[hh * 2 + 1] - f1);
            }
            {
                uint32_t u = Ah[hh * 2 + 1];
                float f0 = __uint_as_float(u << 16);
                float f1 = __uint_as_float(u & 0xffff0000u);
                Al[hh * 2 + 1] = packbf2(v1[hh * 2] - f0, v1[hh * 2 + 1] - f1);
            }
        }

        // ---- 4 n-tiles x 3 plane terms ----
        {
            uint32_t b0, b1;
            b0 = (uint32_t)Bh01.x; b1 = (uint32_t)(Bh01.x >> 32);
            mma16816(acc[0], Ah, b0, b1);
            mma16816(acc[0], Al, b0, b1);
            b0 = (uint32_t)Bl01.x; b1 = (uint32_t)(Bl01.x >> 32);
            mma16816(acc[0], Ah, b0, b1);

            b0 = (uint32_t)Bh01.y; b1 = (uint32_t)(Bh01.y >> 32);
            mma16816(acc[1], Ah, b0, b1);
            mma16816(acc[1], Al, b0, b1);
            b0 = (uint32_t)Bl01.y; b1 = (uint32_t)(Bl01.y >> 32);
            mma16816(acc[1], Ah, b0, b1);

            b0 = (uint32_t)Bh23.x; b1 = (uint32_t)(Bh23.x >> 32);
            mma16816(acc[2], Ah, b0, b1);
            mma16816(acc[2], Al, b0, b1);
            b0 = (uint32_t)Bl23.x; b1 = (uint32_t)(Bl23.x >> 32);
            mma16816(acc[2], Ah, b0, b1);

            b0 = (uint32_t)Bh23.y; b1 = (uint32_t)(Bh23.y >> 32);
            mma16816(acc[3], Ah, b0, b1);
            mma16816(acc[3], Al, b0, b1);
            b0 = (uint32_t)Bl23.y; b1 = (uint32_t)(Bl23.y >> 32);
            mma16816(acc[3], Ah, b0, b1);
        }

        // ---- rotate ----
        sc_cur = sc_nxt;
        Bh01 = nBh01; Bh23 = nBh23;
        Bl01 = nBl01; Bl23 = nBl23;
    }

    // ---- write partial ----
    float* dst = g_part[split];
#pragma unroll
    for (int nt = 0; nt < 4; ++nt) {
        int col = nt * 8 + 2 * q;
        *(float2*)&dst[(row0 + r0) * NF + col] = make_float2(acc[nt][0], acc[nt][1]);
        *(float2*)&dst[(row0 + r1) * NF + col] = make_float2(acc[nt][2], acc[nt][3]);
    }

    // ---- last CTA of this tile reduces all splits (deterministic order) ----
    __threadfence();
    __syncthreads();
    if (tid == 0) {
        int t = atomicAdd(&g_cnt[tile], 1);
        amLast = (t == NSPLIT - 1);
    }
    __syncthreads();
    if (amLast) {
        const float4* xv = (const float4*)(x + row0 * NF);
        float4* ov = (float4*)(out + row0 * NF);
        for (int i = tid; i < MTILE * NF / 4; i += THREADS) {
            float4 o = xv[i];
#pragma unroll
            for (int s = 0; s < NSPLIT; ++s) {
                float4 p = ((const float4*)(g_part[s] + row0 * NF))[i];
                o.x += p.x; o.y += p.y; o.z += p.z; o.w += p.w;
            }
            ov[i] = o;
        }
    }
}

extern "C" void kernel_launch(void* const* d_in, const int* in_sizes, int n_in,
                              void* d_out, int out_size) {
    const float* x = (const float*)d_in[0];
    const float* W = (const float*)d_in[1];
    if (n_in >= 2 && in_sizes[0] == NPOLY * NF && in_sizes[1] == BATCH * NF) {
        x = (const float*)d_in[1];
        W = (const float*)d_in[0];
    }
    float* out = (float*)d_out;

    build_sched_kernel<<<(NRUNS + 127) / 128, 128>>>();
    build_wfrag_kernel<<<(NCHUNKF * 2 * 32 * 4 + 255) / 256, 256>>>(W);
    taylor_mma_kernel<<<NTILES * NSPLIT, THREADS>>>(x, out);
}

// round 14
// speedup vs baseline: 1.0201x; 1.0201x over previous
#include <cuda_runtime.h>
#include <cuda_bf16.h>
#include <cstdint>

#define NF       32
#define NPOLY    6545
#define BATCH    8192
#define MTILE    64
#define NTILES   (BATCH / MTILE)   // 128
#define NRUNS    561
#define NCHUNKP  465               // real chunks (7428 used slots, padded runs)
#define NCHUNKF  466               // +1 ghost chunk (defaults) for branch-free prefetch
#define KPADX    (NCHUNKF * 16)    // 7456 logical slots incl. ghost
#define NSPLIT   6
#define THREADS  128

__device__ int                g_slot2p[KPADX];               // logical slot -> monomial p (-1 = pad)
__device__ unsigned long long g_sched[NCHUNKF * 4];          // [chunk][q]: f|g<<8|m0<<16|m1<<24|m2<<32|m3<<40
__device__ unsigned long long g_wfrag[NCHUNKF * 2 * 32 * 4]; // [chunk][plane][lane][nt] -> {reg0,reg1}
__device__ float              g_part[NSPLIT][BATCH * NF];    // K-split partials

// ---------------------------------------------------------------------------
// Parallel defaults: slot2p = -1 everywhere, sched = all-32 (h=1, m=1 -> 1.0).
// build_sched then overwrites the real 7428 slots / 1857 words.
// ---------------------------------------------------------------------------
__global__ void init_sched_kernel() {
    int i = blockIdx.x * blockDim.x + threadIdx.x;
    if (i < KPADX) g_slot2p[i] = -1;
    if (i < NCHUNKF * 4) g_sched[i] = 0x0000202020202020ull;
}

// ---------------------------------------------------------------------------
// One thread per run (runs have constant h = x_f * x_g):
//   run 0: level<=1, (f,g)=(32,32), L=33, m-list = {32, 0..31}, p = 0..32
//   runs 1..32: level2, f=0..31, g=32, L=f+1, m=0..f, p = 33 + T2(f) + m
//   runs 33..560: level3, (f,g) lex, L=g+1, m=0..g, p = 561 + T3(f) + T2(g) + m
// Runs padded to multiples of 4; group of 4 logical slots = one (chunk,q)
// sched word; physical k-slot = 2q + (e&1) + 8*(e>>1).
// ---------------------------------------------------------------------------
__global__ void build_sched_kernel() {
    int r = blockIdx.x * blockDim.x + threadIdx.x;
    if (r >= NRUNS) return;

    int f, g, L, base_p, off;
    if (r == 0) {
        f = 32; g = 32; L = 33; base_p = 0; off = 0;
    } else if (r <= 32) {
        int ff = r - 1;
        f = ff; g = 32; L = ff + 1;
        base_p = 33 + ff * (ff + 1) / 2;
        off = 36;
        for (int t = 0; t < ff; ++t) off += ((t + 4) / 4) * 4;   // ceil((t+1)/4)*4
    } else {
        int rr = r - 33;                       // = f(f+1)/2 + g
        int ff = (int)((sqrtf(8.0f * (float)rr + 1.0f) - 1.0f) * 0.5f);
        if (ff < 0) ff = 0; if (ff > 31) ff = 31;
        while (ff < 31 && (ff + 1) * (ff + 2) / 2 <= rr) ff++;
        while (ff > 0 && ff * (ff + 1) / 2 > rr) ff--;
        int gg = rr - ff * (ff + 1) / 2;
        f = ff; g = gg; L = gg + 1;
        base_p = 561 + ff * (ff + 1) * (ff + 2) / 6 + gg * (gg + 1) / 2;
        off = 612;                             // 36 + 576 (levels <=2 padded)
        for (int t = 0; t < ff; ++t)
            for (int u = 0; u <= t; ++u) off += ((u + 4) / 4) * 4;
        for (int u = 0; u < gg; ++u) off += ((u + 4) / 4) * 4;
    }

    int P = ((L + 3) / 4) * 4;
    for (int i0 = 0; i0 < P; i0 += 4) {
        unsigned long long sc = (unsigned long long)f | ((unsigned long long)g << 8);
#pragma unroll
        for (int e = 0; e < 4; ++e) {
            int i = i0 + e;
            int m, p;
            if (r == 0) {
                if (i == 0)      { m = 32;    p = 0; }
                else if (i < L)  { m = i - 1; p = i; }
                else             { m = 32;    p = -1; }
            } else {
                if (i < L)       { m = i;     p = base_p + i; }
                else             { m = 32;    p = -1; }
            }
            sc |= (unsigned long long)m << (16 + 8 * e);
            g_slot2p[off + i] = p;
        }
        int s = off + i0;
        g_sched[(s >> 4) * 4 + ((s >> 2) & 3)] = sc;
    }
}

// W fragments for mma.m16n8k16.row.col B (col-major KxN), hi/lo bf16 planes.
// Lane-major layout: [chunk][plane][lane][nt] -> one lane's 4 n-tiles are 32
// contiguous bytes => consumer loads 2x LDG.128 per plane.
// Physical k-slot (2q + j + 8*half) <- logical slot c*16 + q*4 + j + 2*half.
__global__ void build_wfrag_kernel(const float* __restrict__ W) {
    int e = blockIdx.x * blockDim.x + threadIdx.x;
    if (e >= NCHUNKF * 2 * 32 * 4) return;
    int nt   = e & 3;
    int lane = (e >> 2) & 31;
    int pl   = (e >> 7) & 1;
    int c    = e >> 8;
    int q    = lane & 3;
    int n    = nt * 8 + (lane >> 2);

    unsigned long long out = 0;
#pragma unroll
    for (int half = 0; half < 2; ++half) {
        uint32_t reg = 0;
#pragma unroll
        for (int j = 0; j < 2; ++j) {
            int s = c * 16 + q * 4 + j + 2 * half;
            int p = g_slot2p[s];
            float w = (p >= 0) ? W[p * NF + n] : 0.0f;
            __nv_bfloat16 h = __float2bfloat16(w);
            __nv_bfloat16 val = (pl == 0) ? h : __float2bfloat16(w - __bfloat162float(h));
            reg |= (uint32_t)__bfloat16_as_ushort(val) << (16 * j);
        }
        out |= (unsigned long long)reg << (32 * half);
    }
    g_wfrag[e] = out;
}

// ---------------------------------------------------------------------------
__device__ __forceinline__ void mma16816(float* d, const uint32_t* a,
                                         uint32_t b0, uint32_t b1) {
    asm("mma.sync.aligned.m16n8k16.row.col.f32.bf16.bf16.f32 "
        "{%0,%1,%2,%3}, {%4,%5,%6,%7}, {%8,%9}, {%0,%1,%2,%3};"
        : "+f"(d[0]), "+f"(d[1]), "+f"(d[2]), "+f"(d[3])
        : "r"(a[0]), "r"(a[1]), "r"(a[2]), "r"(a[3]), "r"(b0), "r"(b1));
}

__device__ __forceinline__ uint32_t packbf2(float lo, float hi) {
    __nv_bfloat162 t = __floats2bfloat162_rn(lo, hi);   // .x = lo half
    return *(uint32_t*)&t;
}

// ---------------------------------------------------------------------------
// Main fused kernel: CTA = 64-row M-tile x one K-sixth. 4 warps, each a
// 16-row stripe x full N=32. Per chunk per thread: shared h = x_f*x_g ->
// 12 LDS + 10 FMUL. Ghost chunk -> branch-free prefetch. No fences/atomics.
// ---------------------------------------------------------------------------
__global__ __launch_bounds__(THREADS, 6)
void taylor_mma_kernel(const float* __restrict__ x) {
    __shared__ float xt[33][65];   // row stride 65: bank = feat + row (mod 32)

    const int tid   = threadIdx.x;
    const int lane  = tid & 31;
    const int warp  = tid >> 5;          // 0..3
    const int gid   = lane >> 2;         // 0..7
    const int q     = lane & 3;          // 0..3
    const int tile  = blockIdx.x / NSPLIT;
    const int split = blockIdx.x % NSPLIT;
    const int row0  = tile * MTILE;
    const int r0    = warp * 16 + gid;
    const int r1    = r0 + 8;

    for (int e = tid; e < MTILE * NF; e += THREADS) {
        int rr = e >> 5, ii = e & 31;
        xt[ii][rr] = x[(row0 + rr) * NF + ii];
    }
    if (tid < MTILE) xt[32][tid] = 1.0f;
    __syncthreads();

    float acc[4][4];
#pragma unroll
    for (int nt = 0; nt < 4; ++nt)
#pragma unroll
        for (int j = 0; j < 4; ++j) acc[nt][j] = 0.0f;

    // 465 = 6*77 + 3 -> splits 0..2 take 78 chunks, 3..5 take 77
    const int cbase = 77 * split + (split < 3 ? split : 3);
    const int nch   = 77 + (split < 3 ? 1 : 0);
    const float* xr0 = &xt[0][r0];
    const float* xr1 = &xt[0][r1];

    // ---- prologue: load chunk cbase ----
    unsigned long long sc_cur = g_sched[cbase * 4 + q];
    ulonglong2 Bh01, Bh23, Bl01, Bl23;
    {
        const ulonglong2* wh = (const ulonglong2*)(g_wfrag + (((size_t)cbase * 2 + 0) * 32 + lane) * 4);
        const ulonglong2* wl = (const ulonglong2*)(g_wfrag + (((size_t)cbase * 2 + 1) * 32 + lane) * 4);
        Bh01 = wh[0]; Bh23 = wh[1];
        Bl01 = wl[0]; Bl23 = wl[1];
    }

#pragma unroll 2
    for (int i = 0; i < nch; ++i) {
        // ---- prefetch chunk i+1 (ghost chunk keeps this in-bounds) ----
        const int cn = cbase + i + 1;
        const unsigned long long sc_nxt = g_sched[cn * 4 + q];
        const ulonglong2* whn = (const ulonglong2*)(g_wfrag + (((size_t)cn * 2 + 0) * 32 + lane) * 4);
        const ulonglong2* wln = (const ulonglong2*)(g_wfrag + (((size_t)cn * 2 + 1) * 32 + lane) * 4);
        const ulonglong2 nBh01 = whn[0], nBh23 = whn[1];
        const ulonglong2 nBl01 = wln[0], nBl23 = wln[1];

        // ---- evaluate: one shared h per row, 4 m-multiplies per row ----
        const int f  = (int)(sc_cur & 255);
        const int g  = (int)((sc_cur >> 8) & 255);
        const int m0 = (int)((sc_cur >> 16) & 255);
        const int m1 = (int)((sc_cur >> 24) & 255);
        const int m2 = (int)((sc_cur >> 32) & 255);
        const int m3 = (int)((sc_cur >> 40) & 255);
        const float h0 = xr0[f * 65] * xr0[g * 65];
        const float h1 = xr1[f * 65] * xr1[g * 65];
        float v0[4], v1[4];
        v0[0] = h0 * xr0[m0 * 65];  v1[0] = h1 * xr1[m0 * 65];
        v0[1] = h0 * xr0[m1 * 65];  v1[1] = h1 * xr1[m1 * 65];
        v0[2] = h0 * xr0[m2 * 65];  v1[2] = h1 * xr1[m2 * 65];
        v0[3] = h0 * xr0[m3 * 65];  v1[3] = h1 * xr1[m3 * 65];

        // ---- A fragments: hi plane + residual lo plane ----
        uint32_t Ah[4], Al[4];
        Ah[0] = packbf2(v0[0], v0[1]);
        Ah[1] = packbf2(v1[0], v1[1]);
        Ah[2] = packbf2(v0[2], v0[3]);
        Ah[3] = packbf2(v1[2], v1[3]);
#pragma unroll
        for (int hh = 0; hh < 2; ++hh) {
            {
                uint32_t u = Ah[hh * 2];
                float f0 = __uint_as_float(u << 16);
                float f1 = __uint_as_float(u & 0xffff0000u);
                Al[hh * 2] = packbf2(v0[hh * 2] - f0, v0[hh * 2 + 1] - f1);
            }
            {
                uint32_t u = Ah[hh * 2 + 1];
                float f0 = __uint_as_float(u << 16);
                float f1 = __uint_as_float(u & 0xffff0000u);
                Al[hh * 2 + 1] = packbf2(v1[hh * 2] - f0, v1[hh * 2 + 1] - f1);
            }
        }

        // ---- 4 n-tiles x 3 plane terms ----
        {
            uint32_t b0, b1;
            b0 = (uint32_t)Bh01.x; b1 = (uint32_t)(Bh01.x >> 32);
            mma16816(acc[0], Ah, b0, b1);
            mma16816(acc[0], Al, b0, b1);
            b0 = (uint32_t)Bl01.x; b1 = (uint32_t)(Bl01.x >> 32);
            mma16816(acc[0], Ah, b0, b1);

            b0 = (uint32_t)Bh01.y; b1 = (uint32_t)(Bh01.y >> 32);
            mma16816(acc[1], Ah, b0, b1);
            mma16816(acc[1], Al, b0, b1);
            b0 = (uint32_t)Bl01.y; b1 = (uint32_t)(Bl01.y >> 32);
            mma16816(acc[1], Ah, b0, b1);

            b0 = (uint32_t)Bh23.x; b1 = (uint32_t)(Bh23.x >> 32);
            mma16816(acc[2], Ah, b0, b1);
            mma16816(acc[2], Al, b0, b1);
            b0 = (uint32_t)Bl23.x; b1 = (uint32_t)(Bl23.x >> 32);
            mma16816(acc[2], Ah, b0, b1);

            b0 = (uint32_t)Bh23.y; b1 = (uint32_t)(Bh23.y >> 32);
            mma16816(acc[3], Ah, b0, b1);
            mma16816(acc[3], Al, b0, b1);
            b0 = (uint32_t)Bl23.y; b1 = (uint32_t)(Bl23.y >> 32);
            mma16816(acc[3], Ah, b0, b1);
        }

        // ---- rotate ----
        sc_cur = sc_nxt;
        Bh01 = nBh01; Bh23 = nBh23;
        Bl01 = nBl01; Bl23 = nBl23;
    }

    // ---- epilogue: write partial ----
    float* dst = g_part[split];
#pragma unroll
    for (int nt = 0; nt < 4; ++nt) {
        int col = nt * 8 + 2 * q;
        *(float2*)&dst[(row0 + r0) * NF + col] = make_float2(acc[nt][0], acc[nt][1]);
        *(float2*)&dst[(row0 + r1) * NF + col] = make_float2(acc[nt][2], acc[nt][3]);
    }
}

__global__ void reduce_kernel(const float* __restrict__ x, float* __restrict__ out) {
    int i = blockIdx.x * blockDim.x + threadIdx.x;
    if (i >= BATCH * NF / 4) return;
    float4 o = ((const float4*)x)[i];
#pragma unroll
    for (int s = 0; s < NSPLIT; ++s) {
        float4 p = ((const float4*)g_part[s])[i];
        o.x += p.x; o.y += p.y; o.z += p.z; o.w += p.w;
    }
    ((float4*)out)[i] = o;
}

extern "C" void kernel_launch(void* const* d_in, const int* in_sizes, int n_in,
                              void* d_out, int out_size) {
    const float* x = (const float*)d_in[0];
    const float* W = (const float*)d_in[1];
    if (n_in >= 2 && in_sizes[0] == NPOLY * NF && in_sizes[1] == BATCH * NF) {
        x = (const float*)d_in[1];
        W = (const float*)d_in[0];
    }
    float* out = (float*)d_out;

    init_sched_kernel<<<(KPADX + 255) / 256, 256>>>();
    build_sched_kernel<<<(NRUNS + 127) / 128, 128>>>();
    build_wfrag_kernel<<<(NCHUNKF * 2 * 32 * 4 + 255) / 256, 256>>>(W);
    taylor_mma_kernel<<<NTILES * NSPLIT, THREADS>>>(x);
    reduce_kernel<<<(BATCH * NF / 4 + 255) / 256, 256>>>(x, out);
}

// round 15
// speedup vs baseline: 1.2383x; 1.2138x over previous
#include <cuda_runtime.h>
#include <cuda_bf16.h>
#include <cstdint>

#define NF       32
#define NPOLY    6545
#define BATCH    8192
#define MTILE    64
#define NTILES   (BATCH / MTILE)   // 128
#define NRUNS    561
#define NCHUNKP  465               // real chunks (7428 used slots, padded runs)
#define NCHUNKF  466               // +1 ghost chunk (defaults) for branch-free prefetch
#define KPADX    (NCHUNKF * 16)    // 7456 logical slots incl. ghost
#define NSPLIT   6
#define THREADS  128

__device__ int                g_slot2p[KPADX];               // logical slot -> monomial p (-1 = pad)
__device__ unsigned long long g_sched[NCHUNKF * 4];          // [chunk][q]: f|g<<8|m0<<16|m1<<24|m2<<32|m3<<40
// B fragments: [chunk][plane][pair][lane] as ulonglong2 {nt(2*pair), nt(2*pair+1)}
// -> lane reads 16B at lane*16: warp LDG.128 = 512B contiguous (4 wavefronts).
__device__ ulonglong2         g_wfrag2[NCHUNKF * 2 * 2 * 32];
__device__ float              g_part[NSPLIT][BATCH * NF];    // K-split partials

// ---------------------------------------------------------------------------
// Parallel defaults: slot2p = -1 everywhere, sched = all-32 (h=1, m=1 -> 1.0).
// build_sched then overwrites the real 7428 slots / 1857 words.
// ---------------------------------------------------------------------------
__global__ void init_sched_kernel() {
    int i = blockIdx.x * blockDim.x + threadIdx.x;
    if (i < KPADX) g_slot2p[i] = -1;
    if (i < NCHUNKF * 4) g_sched[i] = 0x0000202020202020ull;
}

// ---------------------------------------------------------------------------
// One thread per run (runs have constant h = x_f * x_g):
//   run 0: level<=1, (f,g)=(32,32), L=33, m-list = {32, 0..31}, p = 0..32
//   runs 1..32: level2, f=0..31, g=32, L=f+1, m=0..f, p = 33 + T2(f) + m
//   runs 33..560: level3, (f,g) lex, L=g+1, m=0..g, p = 561 + T3(f) + T2(g) + m
// Runs padded to multiples of 4; group of 4 logical slots = one (chunk,q)
// sched word; physical k-slot = 2q + (e&1) + 8*(e>>1).
// ---------------------------------------------------------------------------
__global__ void build_sched_kernel() {
    int r = blockIdx.x * blockDim.x + threadIdx.x;
    if (r >= NRUNS) return;

    int f, g, L, base_p, off;
    if (r == 0) {
        f = 32; g = 32; L = 33; base_p = 0; off = 0;
    } else if (r <= 32) {
        int ff = r - 1;
        f = ff; g = 32; L = ff + 1;
        base_p = 33 + ff * (ff + 1) / 2;
        off = 36;
        for (int t = 0; t < ff; ++t) off += ((t + 4) / 4) * 4;   // ceil((t+1)/4)*4
    } else {
        int rr = r - 33;                       // = f(f+1)/2 + g
        int ff = (int)((sqrtf(8.0f * (float)rr + 1.0f) - 1.0f) * 0.5f);
        if (ff < 0) ff = 0; if (ff > 31) ff = 31;
        while (ff < 31 && (ff + 1) * (ff + 2) / 2 <= rr) ff++;
        while (ff > 0 && ff * (ff + 1) / 2 > rr) ff--;
        int gg = rr - ff * (ff + 1) / 2;
        f = ff; g = gg; L = gg + 1;
        base_p = 561 + ff * (ff + 1) * (ff + 2) / 6 + gg * (gg + 1) / 2;
        off = 612;                             // 36 + 576 (levels <=2 padded)
        for (int t = 0; t < ff; ++t)
            for (int u = 0; u <= t; ++u) off += ((u + 4) / 4) * 4;
        for (int u = 0; u < gg; ++u) off += ((u + 4) / 4) * 4;
    }

    int P = ((L + 3) / 4) * 4;
    for (int i0 = 0; i0 < P; i0 += 4) {
        unsigned long long sc = (unsigned long long)f | ((unsigned long long)g << 8);
#pragma unroll
        for (int e = 0; e < 4; ++e) {
            int i = i0 + e;
            int m, p;
            if (r == 0) {
                if (i == 0)      { m = 32;    p = 0; }
                else if (i < L)  { m = i - 1; p = i; }
                else             { m = 32;    p = -1; }
            } else {
                if (i < L)       { m = i;     p = base_p + i; }
                else             { m = 32;    p = -1; }
            }
            sc |= (unsigned long long)m << (16 + 8 * e);
            g_slot2p[off + i] = p;
        }
        int s = off + i0;
        g_sched[(s >> 4) * 4 + ((s >> 2) & 3)] = sc;
    }
}

// W fragments for mma.m16n8k16.row.col B (col-major KxN), hi/lo bf16 planes.
// One thread per (chunk, plane, pair, lane): writes the ulonglong2
// {u64 for nt=2*pair, u64 for nt=2*pair+1}.
// Physical k-slot (2q + j + 8*half) <- logical slot c*16 + q*4 + j + 2*half.
__global__ void build_wfrag_kernel(const float* __restrict__ W) {
    int e = blockIdx.x * blockDim.x + threadIdx.x;
    if (e >= NCHUNKF * 2 * 2 * 32) return;
    int lane = e & 31;
    int pi   = (e >> 5) & 1;
    int pl   = (e >> 6) & 1;
    int c    = e >> 7;
    int q    = lane & 3;

    unsigned long long u[2];
#pragma unroll
    for (int t = 0; t < 2; ++t) {
        int nt = 2 * pi + t;
        int n  = nt * 8 + (lane >> 2);
        unsigned long long out = 0;
#pragma unroll
        for (int half = 0; half < 2; ++half) {
            uint32_t reg = 0;
#pragma unroll
            for (int j = 0; j < 2; ++j) {
                int s = c * 16 + q * 4 + j + 2 * half;
                int p = g_slot2p[s];
                float w = (p >= 0) ? W[p * NF + n] : 0.0f;
                __nv_bfloat16 h = __float2bfloat16(w);
                __nv_bfloat16 val = (pl == 0) ? h : __float2bfloat16(w - __bfloat162float(h));
                reg |= (uint32_t)__bfloat16_as_ushort(val) << (16 * j);
            }
            out |= (unsigned long long)reg << (32 * half);
        }
        u[t] = out;
    }
    ulonglong2 v; v.x = u[0]; v.y = u[1];
    g_wfrag2[e] = v;
}

// ---------------------------------------------------------------------------
__device__ __forceinline__ void mma16816(float* d, const uint32_t* a,
                                         uint32_t b0, uint32_t b1) {
    asm("mma.sync.aligned.m16n8k16.row.col.f32.bf16.bf16.f32 "
        "{%0,%1,%2,%3}, {%4,%5,%6,%7}, {%8,%9}, {%0,%1,%2,%3};"
        : "+f"(d[0]), "+f"(d[1]), "+f"(d[2]), "+f"(d[3])
        : "r"(a[0]), "r"(a[1]), "r"(a[2]), "r"(a[3]), "r"(b0), "r"(b1));
}

__device__ __forceinline__ uint32_t packbf2(float lo, float hi) {
    __nv_bfloat162 t = __floats2bfloat162_rn(lo, hi);   // .x = lo half
    return *(uint32_t*)&t;
}

// ---------------------------------------------------------------------------
// Main fused kernel: CTA = 64-row M-tile x one K-sixth. 4 warps, each a
// 16-row stripe x full N=32. Per chunk per thread: shared h = x_f*x_g ->
// 12 LDS + 10 FMUL. B loads: 4x coalesced LDG.128 (512B/warp each).
// Ghost chunk -> branch-free prefetch. No fences/atomics.
// ---------------------------------------------------------------------------
__global__ __launch_bounds__(THREADS, 6)
void taylor_mma_kernel(const float* __restrict__ x) {
    __shared__ float xt[33][65];   // row stride 65: bank = feat + row (mod 32)

    const int tid   = threadIdx.x;
    const int lane  = tid & 31;
    const int warp  = tid >> 5;          // 0..3
    const int gid   = lane >> 2;         // 0..7
    const int q     = lane & 3;          // 0..3
    const int tile  = blockIdx.x / NSPLIT;
    const int split = blockIdx.x % NSPLIT;
    const int row0  = tile * MTILE;
    const int r0    = warp * 16 + gid;
    const int r1    = r0 + 8;

    for (int e = tid; e < MTILE * NF; e += THREADS) {
        int rr = e >> 5, ii = e & 31;
        xt[ii][rr] = x[(row0 + rr) * NF + ii];
    }
    if (tid < MTILE) xt[32][tid] = 1.0f;
    __syncthreads();

    float acc[4][4];
#pragma unroll
    for (int nt = 0; nt < 4; ++nt)
#pragma unroll
        for (int j = 0; j < 4; ++j) acc[nt][j] = 0.0f;

    // 465 = 6*77 + 3 -> splits 0..2 take 78 chunks, 3..5 take 77
    const int cbase = 77 * split + (split < 3 ? split : 3);
    const int nch   = 77 + (split < 3 ? 1 : 0);
    const float* xr0 = &xt[0][r0];
    const float* xr1 = &xt[0][r1];

    // ---- prologue: load chunk cbase ----
    unsigned long long sc_cur = g_sched[cbase * 4 + q];
    ulonglong2 Bh01, Bh23, Bl01, Bl23;
    {
        const ulonglong2* wh = g_wfrag2 + ((size_t)cbase * 2 + 0) * 64 + lane;
        const ulonglong2* wl = g_wfrag2 + ((size_t)cbase * 2 + 1) * 64 + lane;
        Bh01 = wh[0]; Bh23 = wh[32];
        Bl01 = wl[0]; Bl23 = wl[32];
    }

#pragma unroll 2
    for (int i = 0; i < nch; ++i) {
        // ---- prefetch chunk i+1 (ghost chunk keeps this in-bounds) ----
        const int cn = cbase + i + 1;
        const unsigned long long sc_nxt = g_sched[cn * 4 + q];
        const ulonglong2* whn = g_wfrag2 + ((size_t)cn * 2 + 0) * 64 + lane;
        const ulonglong2* wln = g_wfrag2 + ((size_t)cn * 2 + 1) * 64 + lane;
        const ulonglong2 nBh01 = whn[0], nBh23 = whn[32];
        const ulonglong2 nBl01 = wln[0], nBl23 = wln[32];

        // ---- evaluate: one shared h per row, 4 m-multiplies per row ----
        const int f  = (int)(sc_cur & 255);
        const int g  = (int)((sc_cur >> 8) & 255);
        const int m0 = (int)((sc_cur >> 16) & 255);
        const int m1 = (int)((sc_cur >> 24) & 255);
        const int m2 = (int)((sc_cur >> 32) & 255);
        const int m3 = (int)((sc_cur >> 40) & 255);
        const float h0 = xr0[f * 65] * xr0[g * 65];
        const float h1 = xr1[f * 65] * xr1[g * 65];
        float v0[4], v1[4];
        v0[0] = h0 * xr0[m0 * 65];  v1[0] = h1 * xr1[m0 * 65];
        v0[1] = h0 * xr0[m1 * 65];  v1[1] = h1 * xr1[m1 * 65];
        v0[2] = h0 * xr0[m2 * 65];  v1[2] = h1 * xr1[m2 * 65];
        v0[3] = h0 * xr0[m3 * 65];  v1[3] = h1 * xr1[m3 * 65];

        // ---- A fragments: hi plane + residual lo plane ----
        uint32_t Ah[4], Al[4];
        Ah[0] = packbf2(v0[0], v0[1]);
        Ah[1] = packbf2(v1[0], v1[1]);
        Ah[2] = packbf2(v0[2], v0[3]);
        Ah[3] = packbf2(v1[2], v1[3]);
#pragma unroll
        for (int hh = 0; hh < 2; ++hh) {
            {
                uint32_t u = Ah[hh * 2];
                float f0 = __uint_as_float(u << 16);
                float f1 = __uint_as_float(u & 0xffff0000u);
                Al[hh * 2] = packbf2(v0[hh * 2] - f0, v0[hh * 2 + 1] - f1);
            }
            {
                uint32_t u = Ah[hh * 2 + 1];
                float f0 = __uint_as_float(u << 16);
                float f1 = __uint_as_float(u & 0xffff0000u);
                Al[hh * 2 + 1] = packbf2(v1[hh * 2] - f0, v1[hh * 2 + 1] - f1);
            }
        }

        // ---- 4 n-tiles x 3 plane terms ----
        {
            uint32_t b0, b1;
            b0 = (uint32_t)Bh01.x; b1 = (uint32_t)(Bh01.x >> 32);
            mma16816(acc[0], Ah, b0, b1);
            mma16816(acc[0], Al, b0, b1);
            b0 = (uint32_t)Bl01.x; b1 = (uint32_t)(Bl01.x >> 32);
            mma16816(acc[0], Ah, b0, b1);

            b0 = (uint32_t)Bh01.y; b1 = (uint32_t)(Bh01.y >> 32);
            mma16816(acc[1], Ah, b0, b1);
            mma16816(acc[1], Al, b0, b1);
            b0 = (uint32_t)Bl01.y; b1 = (uint32_t)(Bl01.y >> 32);
            mma16816(acc[1], Ah, b0, b1);

            b0 = (uint32_t)Bh23.x; b1 = (uint32_t)(Bh23.x >> 32);
            mma16816(acc[2], Ah, b0, b1);
            mma16816(acc[2], Al, b0, b1);
            b0 = (uint32_t)Bl23.x; b1 = (uint32_t)(Bl23.x >> 32);
            mma16816(acc[2], Ah, b0, b1);

            b0 = (uint32_t)Bh23.y; b1 = (uint32_t)(Bh23.y >> 32);
            mma16816(acc[3], Ah, b0, b1);
            mma16816(acc[3], Al, b0, b1);
            b0 = (uint32_t)Bl23.y; b1 = (uint32_t)(Bl23.y >> 32);
            mma16816(acc[3], Ah, b0, b1);
        }

        // ---- rotate ----
        sc_cur = sc_nxt;
        Bh01 = nBh01; Bh23 = nBh23;
        Bl01 = nBl01; Bl23 = nBl23;
    }

    // ---- epilogue: write partial ----
    float* dst = g_part[split];
#pragma unroll
    for (int nt = 0; nt < 4; ++nt) {
        int col = nt * 8 + 2 * q;
        *(float2*)&dst[(row0 + r0) * NF + col] = make_float2(acc[nt][0], acc[nt][1]);
        *(float2*)&dst[(row0 + r1) * NF + col] = make_float2(acc[nt][2], acc[nt][3]);
    }
}

__global__ void reduce_kernel(const float* __restrict__ x, float* __restrict__ out) {
    int i = blockIdx.x * blockDim.x + threadIdx.x;
    if (i >= BATCH * NF / 4) return;
    float4 o = ((const float4*)x)[i];
#pragma unroll
    for (int s = 0; s < NSPLIT; ++s) {
        float4 p = ((const float4*)g_part[s])[i];
        o.x += p.x; o.y += p.y; o.z += p.z; o.w += p.w;
    }
    ((float4*)out)[i] = o;
}

extern "C" void kernel_launch(void* const* d_in, const int* in_sizes, int n_in,
                              void* d_out, int out_size) {
    const float* x = (const float*)d_in[0];
    const float* W = (const float*)d_in[1];
    if (n_in >= 2 && in_sizes[0] == NPOLY * NF && in_sizes[1] == BATCH * NF) {
        x = (const float*)d_in[1];
        W = (const float*)d_in[0];
    }
    float* out = (float*)d_out;

    init_sched_kernel<<<(KPADX + 255) / 256, 256>>>();
    build_sched_kernel<<<(NRUNS + 127) / 128, 128>>>();
    build_wfrag_kernel<<<(NCHUNKF * 2 * 2 * 32 + 255) / 256, 256>>>(W);
    taylor_mma_kernel<<<NTILES * NSPLIT, THREADS>>>(x);
    reduce_kernel<<<(BATCH * NF / 4 + 255) / 256, 256>>>(x, out);
}

// round 16
// speedup vs baseline: 1.4438x; 1.1660x over previous
#include <cuda_runtime.h>
#include <cuda_bf16.h>
#include <cstdint>

#define NF       32
#define NPOLY    6545
#define BATCH    8192
#define MTILE    64
#define NTILES   (BATCH / MTILE)   // 128
#define NRUNS    561
#define NCHUNKP  465               // real chunks (7428 used slots, padded runs)
#define NCHUNKF  466               // +1 ghost chunk for branch-free prefetch
#define KPADX    (NCHUNKF * 16)    // 7456 logical slots incl. ghost
#define NSPLIT   6
#define THREADS  128
#define SCHED_DEF (32u | (32u << 8) | (32u << 16))

__device__ int        g_slot2p[KPADX];          // logical slot -> monomial p (-1 = pad)
__device__ uint32_t   g_sched32[NCHUNKF * 4];   // [chunk][q]: f | g<<8 | m0<<16 (m0 = i0)
// B fragments: [chunk][plane][pair][lane] as ulonglong2 -> warp LDG.128 = 512B contiguous
__device__ ulonglong2 g_wfrag2[NCHUNKF * 2 * 2 * 32];
__device__ float      g_part[NSPLIT][BATCH * NF];

// S2(n) = sum_{k=1..n} 4*ceil(k/4)  (total padded length of runs of length 1..n)
__device__ __forceinline__ int S2c(int n) {
    int a = n >> 2, b = n & 3;
    return 4 * (2 * a * (a + 1) + b * (a + 1));
}

// ---------------------------------------------------------------------------
// One thread per run (runs have constant h = x_f * x_g). Within a run the
// slot index i IS the m index (run 0 reordered: slot i -> p = i+1 for i<32,
// slot 32 -> p=0 (const), pads -> -1). So every aligned group of 4 slots has
// m = {i0..i0+3}: the main kernel vector-loads x_m with one LDS.128.
// Threads 561..567: default tail/ghost sched words; 568..595: tail slot2p.
// ---------------------------------------------------------------------------
__global__ void build_sched_kernel() {
    int r = blockIdx.x * blockDim.x + threadIdx.x;
    if (r >= 596) return;
    if (r >= 561) {
        if (r < 568) g_sched32[1857 + (r - 561)] = SCHED_DEF;  // words 1857..1863
        else         g_slot2p[7428 + (r - 568)] = -1;          // slots 7428..7455
        return;
    }

    int f, g, L, base_p, off;
    if (r == 0) {
        f = 32; g = 32; L = 33; base_p = 0; off = 0;
    } else if (r <= 32) {
        int ff = r - 1;
        f = ff; g = 32; L = ff + 1;
        base_p = 33 + ff * (ff + 1) / 2;
        off = 36 + S2c(ff);
    } else {
        int rr = r - 33;                       // = f(f+1)/2 + g
        int ff = (int)((sqrtf(8.0f * (float)rr + 1.0f) - 1.0f) * 0.5f);
        if (ff < 0) ff = 0; if (ff > 31) ff = 31;
        while (ff < 31 && (ff + 1) * (ff + 2) / 2 <= rr) ff++;
        while (ff > 0 && ff * (ff + 1) / 2 > rr) ff--;
        int gg = rr - ff * (ff + 1) / 2;
        f = ff; g = gg; L = gg + 1;
        base_p = 561 + ff * (ff + 1) * (ff + 2) / 6 + gg * (gg + 1) / 2;
        off = 612 + S2c(gg);
        for (int t = 1; t <= ff; ++t) off += S2c(t);   // O(32)
    }

    int P = ((L + 3) / 4) * 4;
    for (int i0 = 0; i0 < P; i0 += 4) {
        // m0 = i0 for every run (run-0 reordered) -> sched carries only i0
        uint32_t sc = (uint32_t)f | ((uint32_t)g << 8) | ((uint32_t)i0 << 16);
#pragma unroll
        for (int e = 0; e < 4; ++e) {
            int i = i0 + e;
            int p;
            if (r == 0) p = (i < 32) ? (i + 1) : ((i == 32) ? 0 : -1);
            else        p = (i < L) ? (base_p + i) : -1;
            g_slot2p[off + i] = p;
        }
        int s = off + i0;
        g_sched32[(s >> 4) * 4 + ((s >> 2) & 3)] = sc;
    }
}

// W fragments for mma.m16n8k16.row.col B (col-major KxN), hi/lo bf16 planes.
// One thread per (chunk, plane, pair, lane) -> ulonglong2 {nt=2p, nt=2p+1}.
// Physical k-slot (2q + j + 8*half) <- logical slot c*16 + q*4 + j + 2*half.
__global__ void build_wfrag_kernel(const float* __restrict__ W) {
    int e = blockIdx.x * blockDim.x + threadIdx.x;
    if (e >= NCHUNKF * 2 * 2 * 32) return;
    int lane = e & 31;
    int pi   = (e >> 5) & 1;
    int pl   = (e >> 6) & 1;
    int c    = e >> 7;
    int q    = lane & 3;

    unsigned long long u[2];
#pragma unroll
    for (int t = 0; t < 2; ++t) {
        int nt = 2 * pi + t;
        int n  = nt * 8 + (lane >> 2);
        unsigned long long out = 0;
#pragma unroll
        for (int half = 0; half < 2; ++half) {
            uint32_t reg = 0;
#pragma unroll
            for (int j = 0; j < 2; ++j) {
                int s = c * 16 + q * 4 + j + 2 * half;
                int p = g_slot2p[s];
                float w = (p >= 0) ? W[p * NF + n] : 0.0f;
                __nv_bfloat16 h = __float2bfloat16(w);
                __nv_bfloat16 val = (pl == 0) ? h : __float2bfloat16(w - __bfloat162float(h));
                reg |= (uint32_t)__bfloat16_as_ushort(val) << (16 * j);
            }
            out |= (unsigned long long)reg << (32 * half);
        }
        u[t] = out;
    }
    ulonglong2 v; v.x = u[0]; v.y = u[1];
    g_wfrag2[e] = v;
}

// ---------------------------------------------------------------------------
__device__ __forceinline__ void mma16816(float* d, const uint32_t* a,
                                         uint32_t b0, uint32_t b1) {
    asm("mma.sync.aligned.m16n8k16.row.col.f32.bf16.bf16.f32 "
        "{%0,%1,%2,%3}, {%4,%5,%6,%7}, {%8,%9}, {%0,%1,%2,%3};"
        : "+f"(d[0]), "+f"(d[1]), "+f"(d[2]), "+f"(d[3])
        : "r"(a[0]), "r"(a[1]), "r"(a[2]), "r"(a[3]), "r"(b0), "r"(b1));
}

__device__ __forceinline__ uint32_t packbf2(float lo, float hi) {
    __nv_bfloat162 t = __floats2bfloat162_rn(lo, hi);   // .x = lo half
    return *(uint32_t*)&t;
}

// ---------------------------------------------------------------------------
// Main fused kernel: CTA = 64-row M-tile x one K-sixth. 4 warps x 16 rows x
// full N=32. Row-major x tile -> per chunk per thread: 2 scalar LDS (f,g)
// + 1 LDS.128 (x_{m0..m0+3}) per row = 6 LDS total (was 12).
// ---------------------------------------------------------------------------
__global__ __launch_bounds__(THREADS, 6)
void taylor_mma_kernel(const float* __restrict__ x) {
    // row-major: stride 36 floats (bank = 4*gid + feat; 16B-aligned rows).
    // feats: 0..31 = x, 32 = 1.0 (const), 33..35 = 1.0 (pad-safe dummies).
    __shared__ __align__(16) float xt[MTILE][36];

    const int tid   = threadIdx.x;
    const int lane  = tid & 31;
    const int warp  = tid >> 5;          // 0..3
    const int gid   = lane >> 2;         // 0..7
    const int q     = lane & 3;          // 0..3
    const int tile  = blockIdx.x / NSPLIT;
    const int split = blockIdx.x % NSPLIT;
    const int row0  = tile * MTILE;
    const int r0    = warp * 16 + gid;
    const int r1    = r0 + 8;

    for (int e = tid; e < MTILE * NF; e += THREADS) {
        int rr = e >> 5, ii = e & 31;
        xt[rr][ii] = x[(row0 + rr) * NF + ii];
    }
    if (tid < MTILE) {
        xt[tid][32] = 1.0f; xt[tid][33] = 1.0f;
        xt[tid][34] = 1.0f; xt[tid][35] = 1.0f;
    }
    __syncthreads();

    float acc[4][4];
#pragma unroll
    for (int nt = 0; nt < 4; ++nt)
#pragma unroll
        for (int j = 0; j < 4; ++j) acc[nt][j] = 0.0f;

    // 465 = 6*77 + 3 -> splits 0..2 take 78 chunks, 3..5 take 77
    const int cbase = 77 * split + (split < 3 ? split : 3);
    const int nch   = 77 + (split < 3 ? 1 : 0);
    const float* rp0 = &xt[r0][0];
    const float* rp1 = &xt[r1][0];

    // ---- prologue: load chunk cbase ----
    uint32_t sc_cur = g_sched32[cbase * 4 + q];
    ulonglong2 Bh01, Bh23, Bl01, Bl23;
    {
        const ulonglong2* wh = g_wfrag2 + ((size_t)cbase * 2 + 0) * 64 + lane;
        const ulonglong2* wl = g_wfrag2 + ((size_t)cbase * 2 + 1) * 64 + lane;
        Bh01 = wh[0]; Bh23 = wh[32];
        Bl01 = wl[0]; Bl23 = wl[32];
    }

#pragma unroll 2
    for (int i = 0; i < nch; ++i) {
        // ---- prefetch chunk i+1 (ghost chunk keeps this in-bounds) ----
        const int cn = cbase + i + 1;
        const uint32_t sc_nxt = g_sched32[cn * 4 + q];
        const ulonglong2* whn = g_wfrag2 + ((size_t)cn * 2 + 0) * 64 + lane;
        const ulonglong2* wln = g_wfrag2 + ((size_t)cn * 2 + 1) * 64 + lane;
        const ulonglong2 nBh01 = whn[0], nBh23 = whn[32];
        const ulonglong2 nBl01 = wln[0], nBl23 = wln[32];

        // ---- evaluate: h = x_f*x_g; m-block = one LDS.128 per row ----
        const int f  = (int)(sc_cur & 255);
        const int g  = (int)((sc_cur >> 8) & 255);
        const int m0 = (int)((sc_cur >> 16) & 255);
        const float h0 = rp0[f] * rp0[g];
        const float h1 = rp1[f] * rp1[g];
        const float4 mv0 = *(const float4*)(rp0 + m0);
        const float4 mv1 = *(const float4*)(rp1 + m0);
        float v0[4], v1[4];
        v0[0] = h0 * mv0.x;  v1[0] = h1 * mv1.x;
        v0[1] = h0 * mv0.y;  v1[1] = h1 * mv1.y;
        v0[2] = h0 * mv0.z;  v1[2] = h1 * mv1.z;
        v0[3] = h0 * mv0.w;  v1[3] = h1 * mv1.w;

        // ---- A fragments: hi plane + residual lo plane ----
        uint32_t Ah[4], Al[4];
        Ah[0] = packbf2(v0[0], v0[1]);
        Ah[1] = packbf2(v1[0], v1[1]);
        Ah[2] = packbf2(v0[2], v0[3]);
        Ah[3] = packbf2(v1[2], v1[3]);
#pragma unroll
        for (int hh = 0; hh < 2; ++hh) {
            {
                uint32_t u = Ah[hh * 2];
                float f0 = __uint_as_float(u << 16);
                float f1 = __uint_as_float(u & 0xffff0000u);
                Al[hh * 2] = packbf2(v0[hh * 2] - f0, v0[hh * 2 + 1] - f1);
            }
            {
                uint32_t u = Ah[hh * 2 + 1];
                float f0 = __uint_as_float(u << 16);
                float f1 = __uint_as_float(u & 0xffff0000u);
                Al[hh * 2 + 1] = packbf2(v1[hh * 2] - f0, v1[hh * 2 + 1] - f1);
            }
        }

        // ---- 4 n-tiles x 3 plane terms ----
        {
            uint32_t b0, b1;
            b0 = (uint32_t)Bh01.x; b1 = (uint32_t)(Bh01.x >> 32);
            mma16816(acc[0], Ah, b0, b1);
            mma16816(acc[0], Al, b0, b1);
            b0 = (uint32_t)Bl01.x; b1 = (uint32_t)(Bl01.x >> 32);
            mma16816(acc[0], Ah, b0, b1);

            b0 = (uint32_t)Bh01.y; b1 = (uint32_t)(Bh01.y >> 32);
            mma16816(acc[1], Ah, b0, b1);
            mma16816(acc[1], Al, b0, b1);
            b0 = (uint32_t)Bl01.y; b1 = (uint32_t)(Bl01.y >> 32);
            mma16816(acc[1], Ah, b0, b1);

            b0 = (uint32_t)Bh23.x; b1 = (uint32_t)(Bh23.x >> 32);
            mma16816(acc[2], Ah, b0, b1);
            mma16816(acc[2], Al, b0, b1);
            b0 = (uint32_t)Bl23.x; b1 = (uint32_t)(Bl23.x >> 32);
            mma16816(acc[2], Ah, b0, b1);

            b0 = (uint32_t)Bh23.y; b1 = (uint32_t)(Bh23.y >> 32);
            mma16816(acc[3], Ah, b0, b1);
            mma16816(acc[3], Al, b0, b1);
            b0 = (uint32_t)Bl23.y; b1 = (uint32_t)(Bl23.y >> 32);
            mma16816(acc[3], Ah, b0, b1);
        }

        // ---- rotate ----
        sc_cur = sc_nxt;
        Bh01 = nBh01; Bh23 = nBh23;
        Bl01 = nBl01; Bl23 = nBl23;
    }

    // ---- epilogue: write partial ----
    float* dst = g_part[split];
#pragma unroll
    for (int nt = 0; nt < 4; ++nt) {
        int col = nt * 8 + 2 * q;
        *(float2*)&dst[(row0 + r0) * NF + col] = make_float2(acc[nt][0], acc[nt][1]);
        *(float2*)&dst[(row0 + r1) * NF + col] = make_float2(acc[nt][2], acc[nt][3]);
    }
}

__global__ void reduce_kernel(const float* __restrict__ x, float* __restrict__ out) {
    int i = blockIdx.x * blockDim.x + threadIdx.x;
    if (i >= BATCH * NF / 4) return;
    float4 o = ((const float4*)x)[i];
#pragma unroll
    for (int s = 0; s < NSPLIT; ++s) {
        float4 p = ((const float4*)g_part[s])[i];
        o.x += p.x; o.y += p.y; o.z += p.z; o.w += p.w;
    }
    ((float4*)out)[i] = o;
}

extern "C" void kernel_launch(void* const* d_in, const int* in_sizes, int n_in,
                              void* d_out, int out_size) {
    const float* x = (const float*)d_in[0];
    const float* W = (const float*)d_in[1];
    if (n_in >= 2 && in_sizes[0] == NPOLY * NF && in_sizes[1] == BATCH * NF) {
        x = (const float*)d_in[1];
        W = (const float*)d_in[0];
    }
    float* out = (float*)d_out;

    build_sched_kernel<<<5, 128>>>();
    build_wfrag_kernel<<<(NCHUNKF * 2 * 2 * 32 + 255) / 256, 256>>>(W);
    taylor_mma_kernel<<<NTILES * NSPLIT, THREADS>>>(x);
    reduce_kernel<<<(BATCH * NF / 4 + 255) / 256, 256>>>(x, out);
}

// round 17
// speedup vs baseline: 1.5109x; 1.0464x over previous
#include <cuda_runtime.h>
#include <cuda_bf16.h>
#include <cstdint>

#define NF       32
#define NPOLY    6545
#define BATCH    8192
#define MTILE    64
#define NTILES   (BATCH / MTILE)   // 128
#define NRUNS    561
#define NCHUNKP  465               // real chunks (7428 used slots, padded runs)
#define NCHUNKF  466               // +1 ghost chunk for branch-free prefetch
#define KPADX    (NCHUNKF * 16)    // 7456 logical slots incl. ghost
#define NSPLIT   6
#define THREADS  128
#define SCHED_DEF (32u | (32u << 8) | (32u << 16))

__device__ int        g_slot2p[KPADX];          // logical slot -> monomial p (-1 = pad)
__device__ uint32_t   g_sched32[NCHUNKF * 4];   // [chunk][q]: f | g<<8 | m0<<16 (m0 = i0)
// B fragments: [chunk][plane][pair][lane] as ulonglong2 -> warp LDG.128 = 512B contiguous
__device__ ulonglong2 g_wfrag2[NCHUNKF * 2 * 2 * 32];

// S2(n) = sum_{k=1..n} 4*ceil(k/4)  (total padded length of runs of length 1..n)
__device__ __forceinline__ int S2c(int n) {
    int a = n >> 2, b = n & 3;
    return 4 * (2 * a * (a + 1) + b * (a + 1));
}

// ---------------------------------------------------------------------------
// One thread per run (runs have constant h = x_f * x_g). Within a run the
// slot index i IS the m index (run 0 reordered: slot i -> p = i+1 for i<32,
// slot 32 -> p=0 (const), pads -> -1). So every aligned group of 4 slots has
// m = {i0..i0+3}: the main kernel vector-loads x_m with one LDS.128.
// Threads 561..567: default tail/ghost sched words; 568..595: tail slot2p.
// ---------------------------------------------------------------------------
__global__ void build_sched_kernel() {
    int r = blockIdx.x * blockDim.x + threadIdx.x;
    if (r >= 596) return;
    if (r >= 561) {
        if (r < 568) g_sched32[1857 + (r - 561)] = SCHED_DEF;  // words 1857..1863
        else         g_slot2p[7428 + (r - 568)] = -1;          // slots 7428..7455
        return;
    }

    int f, g, L, base_p, off;
    if (r == 0) {
        f = 32; g = 32; L = 33; base_p = 0; off = 0;
    } else if (r <= 32) {
        int ff = r - 1;
        f = ff; g = 32; L = ff + 1;
        base_p = 33 + ff * (ff + 1) / 2;
        off = 36 + S2c(ff);
    } else {
        int rr = r - 33;                       // = f(f+1)/2 + g
        int ff = (int)((sqrtf(8.0f * (float)rr + 1.0f) - 1.0f) * 0.5f);
        if (ff < 0) ff = 0; if (ff > 31) ff = 31;
        while (ff < 31 && (ff + 1) * (ff + 2) / 2 <= rr) ff++;
        while (ff > 0 && ff * (ff + 1) / 2 > rr) ff--;
        int gg = rr - ff * (ff + 1) / 2;
        f = ff; g = gg; L = gg + 1;
        base_p = 561 + ff * (ff + 1) * (ff + 2) / 6 + gg * (gg + 1) / 2;
        off = 612 + S2c(gg);
        for (int t = 1; t <= ff; ++t) off += S2c(t);   // O(32)
    }

    int P = ((L + 3) / 4) * 4;
    for (int i0 = 0; i0 < P; i0 += 4) {
        // m0 = i0 for every run (run-0 reordered) -> sched carries only i0
        uint32_t sc = (uint32_t)f | ((uint32_t)g << 8) | ((uint32_t)i0 << 16);
#pragma unroll
        for (int e = 0; e < 4; ++e) {
            int i = i0 + e;
            int p;
            if (r == 0) p = (i < 32) ? (i + 1) : ((i == 32) ? 0 : -1);
            else        p = (i < L) ? (base_p + i) : -1;
            g_slot2p[off + i] = p;
        }
        int s = off + i0;
        g_sched32[(s >> 4) * 4 + ((s >> 2) & 3)] = sc;
    }
}

// W fragments for mma.m16n8k16.row.col B (col-major KxN), hi/lo bf16 planes.
// One thread per (chunk, plane, pair, lane) -> ulonglong2 {nt=2p, nt=2p+1}.
// Physical k-slot (2q + j + 8*half) <- logical slot c*16 + q*4 + j + 2*half.
__global__ void build_wfrag_kernel(const float* __restrict__ W) {
    int e = blockIdx.x * blockDim.x + threadIdx.x;
    if (e >= NCHUNKF * 2 * 2 * 32) return;
    int lane = e & 31;
    int pi   = (e >> 5) & 1;
    int pl   = (e >> 6) & 1;
    int c    = e >> 7;
    int q    = lane & 3;

    unsigned long long u[2];
#pragma unroll
    for (int t = 0; t < 2; ++t) {
        int nt = 2 * pi + t;
        int n  = nt * 8 + (lane >> 2);
        unsigned long long out = 0;
#pragma unroll
        for (int half = 0; half < 2; ++half) {
            uint32_t reg = 0;
#pragma unroll
            for (int j = 0; j < 2; ++j) {
                int s = c * 16 + q * 4 + j + 2 * half;
                int p = g_slot2p[s];
                float w = (p >= 0) ? W[p * NF + n] : 0.0f;
                __nv_bfloat16 h = __float2bfloat16(w);
                __nv_bfloat16 val = (pl == 0) ? h : __float2bfloat16(w - __bfloat162float(h));
                reg |= (uint32_t)__bfloat16_as_ushort(val) << (16 * j);
            }
            out |= (unsigned long long)reg << (32 * half);
        }
        u[t] = out;
    }
    ulonglong2 v; v.x = u[0]; v.y = u[1];
    g_wfrag2[e] = v;
}

// out = x (residual term); main kernel atomically accumulates partials on top.
__global__ void init_out_kernel(const float* __restrict__ x, float* __restrict__ out) {
    int i = blockIdx.x * blockDim.x + threadIdx.x;
    if (i < BATCH * NF / 4) ((float4*)out)[i] = ((const float4*)x)[i];
}

// ---------------------------------------------------------------------------
__device__ __forceinline__ void mma16816(float* d, const uint32_t* a,
                                         uint32_t b0, uint32_t b1) {
    asm("mma.sync.aligned.m16n8k16.row.col.f32.bf16.bf16.f32 "
        "{%0,%1,%2,%3}, {%4,%5,%6,%7}, {%8,%9}, {%0,%1,%2,%3};"
        : "+f"(d[0]), "+f"(d[1]), "+f"(d[2]), "+f"(d[3])
        : "r"(a[0]), "r"(a[1]), "r"(a[2]), "r"(a[3]), "r"(b0), "r"(b1));
}

__device__ __forceinline__ uint32_t packbf2(float lo, float hi) {
    __nv_bfloat162 t = __floats2bfloat162_rn(lo, hi);   // .x = lo half
    return *(uint32_t*)&t;
}

// ---------------------------------------------------------------------------
// Main fused kernel: CTA = 64-row M-tile x one K-sixth. 4 warps x 16 rows x
// full N=32. Row-major x tile -> per chunk per thread: 2 scalar LDS (f,g)
// + 1 LDS.128 (x_{m0..m0+3}) per row = 6 LDS total. Epilogue: RED.ADD into
// out (contention degree NSPLIT=6 spread over 2048 addrs/tile; order jitter
// ~1e-7, far under the 1e-3 threshold).
// ---------------------------------------------------------------------------
__global__ __launch_bounds__(THREADS, 6)
void taylor_mma_kernel(const float* __restrict__ x, float* __restrict__ out) {
    // row-major: stride 36 floats (bank = 4*gid + feat; 16B-aligned rows).
    // feats: 0..31 = x, 32 = 1.0 (const), 33..35 = 1.0 (pad-safe dummies).
    __shared__ __align__(16) float xt[MTILE][36];

    const int tid   = threadIdx.x;
    const int lane  = tid & 31;
    const int warp  = tid >> 5;          // 0..3
    const int gid   = lane >> 2;         // 0..7
    const int q     = lane & 3;          // 0..3
    const int tile  = blockIdx.x / NSPLIT;
    const int split = blockIdx.x % NSPLIT;
    const int row0  = tile * MTILE;
    const int r0    = warp * 16 + gid;
    const int r1    = r0 + 8;

    for (int e = tid; e < MTILE * NF; e += THREADS) {
        int rr = e >> 5, ii = e & 31;
        xt[rr][ii] = x[(row0 + rr) * NF + ii];
    }
    if (tid < MTILE) {
        xt[tid][32] = 1.0f; xt[tid][33] = 1.0f;
        xt[tid][34] = 1.0f; xt[tid][35] = 1.0f;
    }
    __syncthreads();

    float acc[4][4];
#pragma unroll
    for (int nt = 0; nt < 4; ++nt)
#pragma unroll
        for (int j = 0; j < 4; ++j) acc[nt][j] = 0.0f;

    // 465 = 6*77 + 3 -> splits 0..2 take 78 chunks, 3..5 take 77
    const int cbase = 77 * split + (split < 3 ? split : 3);
    const int nch   = 77 + (split < 3 ? 1 : 0);
    const float* rp0 = &xt[r0][0];
    const float* rp1 = &xt[r1][0];

    // ---- prologue: load chunk cbase ----
    uint32_t sc_cur = g_sched32[cbase * 4 + q];
    ulonglong2 Bh01, Bh23, Bl01, Bl23;
    {
        const ulonglong2* wh = g_wfrag2 + ((size_t)cbase * 2 + 0) * 64 + lane;
        const ulonglong2* wl = g_wfrag2 + ((size_t)cbase * 2 + 1) * 64 + lane;
        Bh01 = wh[0]; Bh23 = wh[32];
        Bl01 = wl[0]; Bl23 = wl[32];
    }

#pragma unroll 2
    for (int i = 0; i < nch; ++i) {
        // ---- prefetch chunk i+1 (ghost chunk keeps this in-bounds) ----
        const int cn = cbase + i + 1;
        const uint32_t sc_nxt = g_sched32[cn * 4 + q];
        const ulonglong2* whn = g_wfrag2 + ((size_t)cn * 2 + 0) * 64 + lane;
        const ulonglong2* wln = g_wfrag2 + ((size_t)cn * 2 + 1) * 64 + lane;
        const ulonglong2 nBh01 = whn[0], nBh23 = whn[32];
        const ulonglong2 nBl01 = wln[0], nBl23 = wln[32];

        // ---- evaluate: h = x_f*x_g; m-block = one LDS.128 per row ----
        const int f  = (int)(sc_cur & 255);
        const int g  = (int)((sc_cur >> 8) & 255);
        const int m0 = (int)((sc_cur >> 16) & 255);
        const float h0 = rp0[f] * rp0[g];
        const float h1 = rp1[f] * rp1[g];
        const float4 mv0 = *(const float4*)(rp0 + m0);
        const float4 mv1 = *(const float4*)(rp1 + m0);
        float v0[4], v1[4];
        v0[0] = h0 * mv0.x;  v1[0] = h1 * mv1.x;
        v0[1] = h0 * mv0.y;  v1[1] = h1 * mv1.y;
        v0[2] = h0 * mv0.z;  v1[2] = h1 * mv1.z;
        v0[3] = h0 * mv0.w;  v1[3] = h1 * mv1.w;

        // ---- A fragments: hi plane + residual lo plane ----
        uint32_t Ah[4], Al[4];
        Ah[0] = packbf2(v0[0], v0[1]);
        Ah[1] = packbf2(v1[0], v1[1]);
        Ah[2] = packbf2(v0[2], v0[3]);
        Ah[3] = packbf2(v1[2], v1[3]);
#pragma unroll
        for (int hh = 0; hh < 2; ++hh) {
            {
                uint32_t u = Ah[hh * 2];
                float f0 = __uint_as_float(u << 16);
                float f1 = __uint_as_float(u & 0xffff0000u);
                Al[hh * 2] = packbf2(v0[hh * 2] - f0, v0[hh * 2 + 1] - f1);
            }
            {
                uint32_t u = Ah[hh * 2 + 1];
                float f0 = __uint_as_float(u << 16);
                float f1 = __uint_as_float(u & 0xffff0000u);
                Al[hh * 2 + 1] = packbf2(v1[hh * 2] - f0, v1[hh * 2 + 1] - f1);
            }
        }

        // ---- 4 n-tiles x 3 plane terms ----
        {
            uint32_t b0, b1;
            b0 = (uint32_t)Bh01.x; b1 = (uint32_t)(Bh01.x >> 32);
            mma16816(acc[0], Ah, b0, b1);
            mma16816(acc[0], Al, b0, b1);
            b0 = (uint32_t)Bl01.x; b1 = (uint32_t)(Bl01.x >> 32);
            mma16816(acc[0], Ah, b0, b1);

            b0 = (uint32_t)Bh01.y; b1 = (uint32_t)(Bh01.y >> 32);
            mma16816(acc[1], Ah, b0, b1);
            mma16816(acc[1], Al, b0, b1);
            b0 = (uint32_t)Bl01.y; b1 = (uint32_t)(Bl01.y >> 32);
            mma16816(acc[1], Ah, b0, b1);

            b0 = (uint32_t)Bh23.x; b1 = (uint32_t)(Bh23.x >> 32);
            mma16816(acc[2], Ah, b0, b1);
            mma16816(acc[2], Al, b0, b1);
            b0 = (uint32_t)Bl23.x; b1 = (uint32_t)(Bl23.x >> 32);
            mma16816(acc[2], Ah, b0, b1);

            b0 = (uint32_t)Bh23.y; b1 = (uint32_t)(Bh23.y >> 32);
            mma16816(acc[3], Ah, b0, b1);
            mma16816(acc[3], Al, b0, b1);
            b0 = (uint32_t)Bl23.y; b1 = (uint32_t)(Bl23.y >> 32);
            mma16816(acc[3], Ah, b0, b1);
        }

        // ---- rotate ----
        sc_cur = sc_nxt;
        Bh01 = nBh01; Bh23 = nBh23;
        Bl01 = nBl01; Bl23 = nBl23;
    }

    // ---- epilogue: accumulate into out via RED.ADD (no return value) ----
#pragma unroll
    for (int nt = 0; nt < 4; ++nt) {
        int col = nt * 8 + 2 * q;
        atomicAdd(&out[(row0 + r0) * NF + col],     acc[nt][0]);
        atomicAdd(&out[(row0 + r0) * NF + col + 1], acc[nt][1]);
        atomicAdd(&out[(row0 + r1) * NF + col],     acc[nt][2]);
        atomicAdd(&out[(row0 + r1) * NF + col + 1], acc[nt][3]);
    }
}

extern "C" void kernel_launch(void* const* d_in, const int* in_sizes, int n_in,
                              void* d_out, int out_size) {
    const float* x = (const float*)d_in[0];
    const float* W = (const float*)d_in[1];
    if (n_in >= 2 && in_sizes[0] == NPOLY * NF && in_sizes[1] == BATCH * NF) {
        x = (const float*)d_in[1];
        W = (const float*)d_in[0];
    }
    float* out = (float*)d_out;

    build_sched_kernel<<<5, 128>>>();
    build_wfrag_kernel<<<(NCHUNKF * 2 * 2 * 32 + 255) / 256, 256>>>(W);
    init_out_kernel<<<(BATCH * NF / 4 + 255) / 256, 256>>>(x, out);
    taylor_mma_kernel<<<NTILES * NSPLIT, THREADS>>>(x, out);
}